// round 15
// baseline (speedup 1.0000x reference)
#include <cuda_runtime.h>
#include <cuda_bf16.h>
#include <cstdint>

// out[n, e] = tanh( sum_d input[n, d] * trans[urls[n], d, e] + bias[urls[n], e] )
// input [16,256,256] f32, urls [16,256] i32, trans [2000,256,256] f32, bias [2000,256] f32.
//
// v15: round-11 winner (fastest measured main kernel: 79.5us @ DRAM 75%)
//      + Programmatic Dependent Launch: the main kernel launches while prep
//      is still running and griddepcontrol.wait-s just before touching prep
//      outputs, hiding most of the prep + launch-gap overhead.

#define D 256
#define N_TOKENS 4096
#define N_URLS 2000
#define CHUNK 8
#define ROWS_PER_STAGE 16
#define STAGE_FLOATS (ROWS_PER_STAGE * D)      // 4096 floats = 16KB
#define STAGE_BYTES  (STAGE_FLOATS * 4)
#define N_STAGES     (D / ROWS_PER_STAGE)      // 16 stages per matrix
#define NBUF 2
#define GRID_MAIN    (148 * 5)
#define MAX_MY 4      // nitems <= 2000 < 740*4

// ---- scratch ----
__device__ int g_counts[N_URLS];
__device__ int g_offsets[N_URLS];
__device__ int g_token_list[N_TOKENS];
__device__ int g_items[N_TOKENS];     // (url << 12) | cbase
__device__ int g_nitems;

// ---- PTX helpers ----
__device__ __forceinline__ uint32_t smem_u32(const void* p) {
    return (uint32_t)__cvta_generic_to_shared(p);
}
__device__ __forceinline__ void mbar_init(uint32_t addr, uint32_t count) {
    asm volatile("mbarrier.init.shared.b64 [%0], %1;" :: "r"(addr), "r"(count) : "memory");
}
__device__ __forceinline__ void mbar_expect_tx(uint32_t addr, uint32_t bytes) {
    asm volatile("mbarrier.arrive.expect_tx.shared.b64 _, [%0], %1;"
                 :: "r"(addr), "r"(bytes) : "memory");
}
__device__ __forceinline__ void bulk_g2s(uint32_t dst, const void* src,
                                         uint32_t bytes, uint32_t mbar) {
    asm volatile("cp.async.bulk.shared::cta.global.mbarrier::complete_tx::bytes "
                 "[%0], [%1], %2, [%3];"
                 :: "r"(dst), "l"(src), "r"(bytes), "r"(mbar) : "memory");
}
__device__ __forceinline__ void mbar_wait(uint32_t addr, uint32_t parity) {
    asm volatile(
        "{\n\t"
        ".reg .pred P1;\n\t"
        "WAIT_LOOP_%=:\n\t"
        "mbarrier.try_wait.parity.acquire.cta.shared::cta.b64 P1, [%0], %1, 0x989680;\n\t"
        "@P1 bra.uni WAIT_DONE_%=;\n\t"
        "bra.uni WAIT_LOOP_%=;\n\t"
        "WAIT_DONE_%=:\n\t"
        "}"
        :: "r"(addr), "r"(parity) : "memory");
}

// ---- warp-shuffle inclusive scan ----
__device__ __forceinline__ int warp_incl_scan(int v, int lane) {
    #pragma unroll
    for (int s = 1; s < 32; s <<= 1) {
        int u = __shfl_up_sync(0xffffffffu, v, s);
        if (lane >= s) v += u;
    }
    return v;
}

// ---- fused prep: histogram + 2 scans + scatter + item list, one CTA ----
__global__ __launch_bounds__(1024)
void prep_kernel(const int* __restrict__ urls)
{
    __shared__ int s_cnt[N_URLS];
    __shared__ int s_off[N_URLS];
    __shared__ int s_cur[N_URLS];
    __shared__ int s_wsum[32];
    __shared__ int s_wsum2[32];

    const int t = threadIdx.x;
    const int lane = t & 31, wid = t >> 5;

    for (int i = t; i < N_URLS; i += 1024) { s_cnt[i] = 0; s_cur[i] = 0; }
    __syncthreads();
    for (int n = t; n < N_TOKENS; n += 1024) atomicAdd(&s_cnt[urls[n]], 1);
    __syncthreads();

    const int i0 = 2 * t, i1 = 2 * t + 1;
    const int c0 = (i0 < N_URLS) ? s_cnt[i0] : 0;
    const int c1 = (i1 < N_URLS) ? s_cnt[i1] : 0;

    // scan 1: token offsets
    const int pair = c0 + c1;
    int incl = warp_incl_scan(pair, lane);
    if (lane == 31) s_wsum[wid] = incl;
    __syncthreads();
    if (wid == 0) {
        int v = s_wsum[lane];
        int wi = warp_incl_scan(v, lane);
        s_wsum[lane] = wi - v;
    }
    __syncthreads();
    const int excl = s_wsum[wid] + incl - pair;
    if (i0 < N_URLS) { s_off[i0] = excl;      g_offsets[i0] = excl;      g_counts[i0] = c0; }
    if (i1 < N_URLS) { s_off[i1] = excl + c0; g_offsets[i1] = excl + c0; g_counts[i1] = c1; }
    __syncthreads();

    for (int n = t; n < N_TOKENS; n += 1024) {
        const int u = urls[n];
        const int pos = atomicAdd(&s_cur[u], 1);
        g_token_list[s_off[u] + pos] = n;
    }

    // scan 2: item offsets (ceil(count/8) per url)
    const int nch0 = (c0 + CHUNK - 1) >> 3;
    const int nch1 = (c1 + CHUNK - 1) >> 3;
    const int pair2 = nch0 + nch1;
    int incl2 = warp_incl_scan(pair2, lane);
    if (lane == 31) s_wsum2[wid] = incl2;
    __syncthreads();
    if (wid == 0) {
        int v = s_wsum2[lane];
        int wi = warp_incl_scan(v, lane);
        s_wsum2[lane] = wi - v;
    }
    __syncthreads();
    const int excl2 = s_wsum2[wid] + incl2 - pair2;
    if (i0 < N_URLS)
        for (int j = 0; j < nch0; j++) g_items[excl2 + j] = (i0 << 12) | (j * CHUNK);
    if (i1 < N_URLS)
        for (int j = 0; j < nch1; j++) g_items[excl2 + nch0 + j] = (i1 << 12) | (j * CHUNK);
    if (t == 1023) g_nitems = s_wsum2[31] + incl2;

    // release dependent (main) grid as soon as all outputs are visible
    __syncthreads();
    __threadfence();
    if (t == 0)
        asm volatile("griddepcontrol.launch_dependents;");
}

// ---- main: persistent CTAs, continuous 2x16KB bulk-async ring ----
// 128 threads; thread t owns output columns t and t+128.
// k<=4 path: 8 accumulators (proven fast loop); k>=5 path: 16 accumulators.
__global__ __launch_bounds__(128)
void grouped_kernel(const float* __restrict__ inp,
                    const float* __restrict__ trans,
                    const float* __restrict__ bias,
                    float*       __restrict__ out)
{
    __shared__ float  T_s[NBUF][STAGE_FLOATS];  // 2 x 16KB ring
    __shared__ float4 xs[D * 2];                // 8KB
    __shared__ int    tok_s[CHUNK];
    __shared__ __align__(8) unsigned long long mbar[NBUF];

    const int tid = threadIdx.x;
    const uint32_t mb_base = smem_u32(&mbar[0]);
    const uint32_t tb_base = smem_u32(&T_s[0][0]);

    // prep-independent setup runs while prep kernel is still executing
    if (tid == 0) {
        #pragma unroll
        for (int b = 0; b < NBUF; b++) mbar_init(mb_base + b * 8, 1);
    }
    __syncthreads();

    // wait for prep's outputs before touching them
    asm volatile("griddepcontrol.wait;" ::: "memory");

    const int nitems = g_nitems;
    int n_my = 0;
    int my_items[MAX_MY];
    for (int unit = blockIdx.x; unit < nitems && n_my < MAX_MY; unit += GRID_MAIN)
        my_items[n_my++] = g_items[unit];
    if (n_my == 0) return;

    const int total = n_my * N_STAGES;
    uint32_t phases = 0;

    // prologue: fill ring (producer runs ahead across unit boundaries)
    if (tid == 0) {
        #pragma unroll
        for (int g = 0; g < NBUF; g++) {
            if (g < total) {
                const float* src = trans
                    + (size_t)(my_items[g >> 4] >> 12) * (D * D)
                    + (size_t)(g & (N_STAGES - 1)) * STAGE_FLOATS;
                mbar_expect_tx(mb_base + g * 8, STAGE_BYTES);
                bulk_g2s(tb_base + g * STAGE_BYTES, src, STAGE_BYTES, mb_base + g * 8);
            }
        }
    }

    int g = 0;
    for (int mi = 0; mi < n_my; mi++) {
        const int item  = my_items[mi];
        const int u     = item >> 12;
        const int cbase = item & 0xFFF;
        const int k     = min(CHUNK, g_counts[u] - cbase);
        const int boff  = g_offsets[u];

        __syncthreads();   // prev epilogue done before tok_s/xs rewrite
        if (tid < CHUNK)
            tok_s[tid] = (tid < k) ? g_token_list[boff + cbase + tid] : 0;
        __syncthreads();

        const float b0 = bias[(size_t)u * D + tid];
        const float b1 = bias[(size_t)u * D + tid + 128];

        if (k <= 4) {
            // ---- fast path ----
            for (int d = tid; d < D; d += 128) {
                float4 v;
                v.x =           inp[(size_t)tok_s[0] * D + d];
                v.y = (k > 1) ? inp[(size_t)tok_s[1] * D + d] : 0.f;
                v.z = (k > 2) ? inp[(size_t)tok_s[2] * D + d] : 0.f;
                v.w = (k > 3) ? inp[(size_t)tok_s[3] * D + d] : 0.f;
                xs[d] = v;
            }
            __syncthreads();

            float4 acc0 = make_float4(0.f, 0.f, 0.f, 0.f);
            float4 acc1 = make_float4(0.f, 0.f, 0.f, 0.f);

            for (int ls = 0; ls < N_STAGES; ls++, g++) {
                const int b = g & (NBUF - 1);
                mbar_wait(mb_base + b * 8, (phases >> b) & 1u);
                phases ^= (1u << b);

                const float* buf = T_s[b];
                const int dbase = ls * ROWS_PER_STAGE;
                #pragma unroll 4
                for (int r = 0; r < ROWS_PER_STAGE; r++) {
                    const float4 x = xs[dbase + r];
                    const float t0 = buf[r * D + tid];
                    const float t1 = buf[r * D + tid + 128];
                    acc0.x = fmaf(x.x, t0, acc0.x);
                    acc0.y = fmaf(x.y, t0, acc0.y);
                    acc0.z = fmaf(x.z, t0, acc0.z);
                    acc0.w = fmaf(x.w, t0, acc0.w);
                    acc1.x = fmaf(x.x, t1, acc1.x);
                    acc1.y = fmaf(x.y, t1, acc1.y);
                    acc1.z = fmaf(x.z, t1, acc1.z);
                    acc1.w = fmaf(x.w, t1, acc1.w);
                }
                __syncthreads();
                if (tid == 0 && g + NBUF < total) {
                    const int gn = g + NBUF;
                    const float* src = trans
                        + (size_t)(my_items[gn >> 4] >> 12) * (D * D)
                        + (size_t)(gn & (N_STAGES - 1)) * STAGE_FLOATS;
                    mbar_expect_tx(mb_base + b * 8, STAGE_BYTES);
                    bulk_g2s(tb_base + b * STAGE_BYTES, src, STAGE_BYTES, mb_base + b * 8);
                }
            }

            const float* a0 = (const float*)&acc0;
            const float* a1 = (const float*)&acc1;
            #pragma unroll
            for (int kk = 0; kk < 4; kk++) {
                if (kk < k) {
                    const size_t nb = (size_t)tok_s[kk] * D;
                    out[nb + tid]       = tanhf(a0[kk] + b0);
                    out[nb + tid + 128] = tanhf(a1[kk] + b1);
                }
            }
        } else {
            // ---- heavy path: 5..8 tokens, one matrix stream ----
            for (int d = tid; d < D; d += 128) {
                float4 lo, hi;
                lo.x =           inp[(size_t)tok_s[0] * D + d];
                lo.y =           inp[(size_t)tok_s[1] * D + d];
                lo.z =           inp[(size_t)tok_s[2] * D + d];
                lo.w =           inp[(size_t)tok_s[3] * D + d];
                hi.x =           inp[(size_t)tok_s[4] * D + d];
                hi.y = (k > 5) ? inp[(size_t)tok_s[5] * D + d] : 0.f;
                hi.z = (k > 6) ? inp[(size_t)tok_s[6] * D + d] : 0.f;
                hi.w = (k > 7) ? inp[(size_t)tok_s[7] * D + d] : 0.f;
                xs[d * 2]     = lo;
                xs[d * 2 + 1] = hi;
            }
            __syncthreads();

            float accA[CHUNK], accB[CHUNK];
            #pragma unroll
            for (int q = 0; q < CHUNK; q++) { accA[q] = 0.f; accB[q] = 0.f; }

            for (int ls = 0; ls < N_STAGES; ls++, g++) {
                const int b = g & (NBUF - 1);
                mbar_wait(mb_base + b * 8, (phases >> b) & 1u);
                phases ^= (1u << b);

                const float* buf = T_s[b];
                const int dbase = ls * ROWS_PER_STAGE;
                #pragma unroll 2
                for (int r = 0; r < ROWS_PER_STAGE; r++) {
                    const float4 xlo = xs[(dbase + r) * 2];
                    const float4 xhi = xs[(dbase + r) * 2 + 1];
                    const float t0 = buf[r * D + tid];
                    const float t1 = buf[r * D + tid + 128];
                    accA[0] = fmaf(xlo.x, t0, accA[0]);
                    accA[1] = fmaf(xlo.y, t0, accA[1]);
                    accA[2] = fmaf(xlo.z, t0, accA[2]);
                    accA[3] = fmaf(xlo.w, t0, accA[3]);
                    accA[4] = fmaf(xhi.x, t0, accA[4]);
                    accA[5] = fmaf(xhi.y, t0, accA[5]);
                    accA[6] = fmaf(xhi.z, t0, accA[6]);
                    accA[7] = fmaf(xhi.w, t0, accA[7]);
                    accB[0] = fmaf(xlo.x, t1, accB[0]);
                    accB[1] = fmaf(xlo.y, t1, accB[1]);
                    accB[2] = fmaf(xlo.z, t1, accB[2]);
                    accB[3] = fmaf(xlo.w, t1, accB[3]);
                    accB[4] = fmaf(xhi.x, t1, accB[4]);
                    accB[5] = fmaf(xhi.y, t1, accB[5]);
                    accB[6] = fmaf(xhi.z, t1, accB[6]);
                    accB[7] = fmaf(xhi.w, t1, accB[7]);
                }
                __syncthreads();
                if (tid == 0 && g + NBUF < total) {
                    const int gn = g + NBUF;
                    const float* src = trans
                        + (size_t)(my_items[gn >> 4] >> 12) * (D * D)
                        + (size_t)(gn & (N_STAGES - 1)) * STAGE_FLOATS;
                    mbar_expect_tx(mb_base + b * 8, STAGE_BYTES);
                    bulk_g2s(tb_base + b * STAGE_BYTES, src, STAGE_BYTES, mb_base + b * 8);
                }
            }

            #pragma unroll
            for (int q = 0; q < CHUNK; q++) {
                if (q < k) {
                    const size_t nb = (size_t)tok_s[q] * D;
                    out[nb + tid]       = tanhf(accA[q] + b0);
                    out[nb + tid + 128] = tanhf(accB[q] + b1);
                }
            }
        }
    }
}

extern "C" void kernel_launch(void* const* d_in, const int* in_sizes, int n_in,
                              void* d_out, int out_size)
{
    const float* inp   = (const float*)d_in[0];
    const int*   urls  = (const int*)  d_in[1];
    const float* trans = (const float*)d_in[2];
    const float* bias  = (const float*)d_in[3];
    float*       out   = (float*)      d_out;

    prep_kernel<<<1, 1024>>>(urls);

    // main kernel with Programmatic Dependent Launch: overlaps its launch and
    // prep-independent prologue with the prep kernel's execution.
    cudaLaunchConfig_t cfg = {};
    cfg.gridDim  = dim3(GRID_MAIN, 1, 1);
    cfg.blockDim = dim3(128, 1, 1);
    cfg.dynamicSmemBytes = 0;
    cfg.stream = 0;   // legacy default stream (same as prep)
    cudaLaunchAttribute attrs[1];
    attrs[0].id = cudaLaunchAttributeProgrammaticStreamSerialization;
    attrs[0].val.programmaticStreamSerializationAllowed = 1;
    cfg.attrs = attrs;
    cfg.numAttrs = 1;
    cudaLaunchKernelEx(&cfg, grouped_kernel, inp, trans, bias, out);
}

// round 16
// speedup vs baseline: 1.0126x; 1.0126x over previous
#include <cuda_runtime.h>
#include <cuda_bf16.h>
#include <cstdint>

// out[n, e] = tanh( sum_d input[n, d] * trans[urls[n], d, e] + bias[urls[n], e] )
// input [16,256,256] f32, urls [16,256] i32, trans [2000,256,256] f32, bias [2000,256] f32.
//
// v16: round-11 winner main kernel (79.5us @ DRAM 75%) + PDL done right:
//      prep fires griddepcontrol.launch_dependents at its FIRST instruction,
//      so the main grid's launch/ramp overlaps prep execution; the main grid
//      blocks at griddepcontrol.wait (releases on prep completion) before
//      touching prep outputs.

#define D 256
#define N_TOKENS 4096
#define N_URLS 2000
#define CHUNK 8
#define ROWS_PER_STAGE 16
#define STAGE_FLOATS (ROWS_PER_STAGE * D)      // 4096 floats = 16KB
#define STAGE_BYTES  (STAGE_FLOATS * 4)
#define N_STAGES     (D / ROWS_PER_STAGE)      // 16 stages per matrix
#define NBUF 2
#define GRID_MAIN    (148 * 5)
#define MAX_MY 4      // nitems <= 2000 < 740*4

// ---- scratch ----
__device__ int g_counts[N_URLS];
__device__ int g_offsets[N_URLS];
__device__ int g_token_list[N_TOKENS];
__device__ int g_items[N_TOKENS];     // (url << 12) | cbase
__device__ int g_nitems;

// ---- PTX helpers ----
__device__ __forceinline__ uint32_t smem_u32(const void* p) {
    return (uint32_t)__cvta_generic_to_shared(p);
}
__device__ __forceinline__ void mbar_init(uint32_t addr, uint32_t count) {
    asm volatile("mbarrier.init.shared.b64 [%0], %1;" :: "r"(addr), "r"(count) : "memory");
}
__device__ __forceinline__ void mbar_expect_tx(uint32_t addr, uint32_t bytes) {
    asm volatile("mbarrier.arrive.expect_tx.shared.b64 _, [%0], %1;"
                 :: "r"(addr), "r"(bytes) : "memory");
}
__device__ __forceinline__ void bulk_g2s(uint32_t dst, const void* src,
                                         uint32_t bytes, uint32_t mbar) {
    asm volatile("cp.async.bulk.shared::cta.global.mbarrier::complete_tx::bytes "
                 "[%0], [%1], %2, [%3];"
                 :: "r"(dst), "l"(src), "r"(bytes), "r"(mbar) : "memory");
}
__device__ __forceinline__ void mbar_wait(uint32_t addr, uint32_t parity) {
    asm volatile(
        "{\n\t"
        ".reg .pred P1;\n\t"
        "WAIT_LOOP_%=:\n\t"
        "mbarrier.try_wait.parity.acquire.cta.shared::cta.b64 P1, [%0], %1, 0x989680;\n\t"
        "@P1 bra.uni WAIT_DONE_%=;\n\t"
        "bra.uni WAIT_LOOP_%=;\n\t"
        "WAIT_DONE_%=:\n\t"
        "}"
        :: "r"(addr), "r"(parity) : "memory");
}

// ---- warp-shuffle inclusive scan ----
__device__ __forceinline__ int warp_incl_scan(int v, int lane) {
    #pragma unroll
    for (int s = 1; s < 32; s <<= 1) {
        int u = __shfl_up_sync(0xffffffffu, v, s);
        if (lane >= s) v += u;
    }
    return v;
}

// ---- fused prep: histogram + 2 scans + scatter + item list, one CTA ----
__global__ __launch_bounds__(1024)
void prep_kernel(const int* __restrict__ urls)
{
    // Fire the dependent-launch trigger IMMEDIATELY: the main grid's
    // launch/ramp then overlaps this kernel's execution. Correctness is
    // carried by griddepcontrol.wait in the main kernel (releases on this
    // grid's completion, when all our global stores are visible).
    asm volatile("griddepcontrol.launch_dependents;");

    __shared__ int s_cnt[N_URLS];
    __shared__ int s_off[N_URLS];
    __shared__ int s_cur[N_URLS];
    __shared__ int s_wsum[32];
    __shared__ int s_wsum2[32];

    const int t = threadIdx.x;
    const int lane = t & 31, wid = t >> 5;

    for (int i = t; i < N_URLS; i += 1024) { s_cnt[i] = 0; s_cur[i] = 0; }
    __syncthreads();
    for (int n = t; n < N_TOKENS; n += 1024) atomicAdd(&s_cnt[urls[n]], 1);
    __syncthreads();

    const int i0 = 2 * t, i1 = 2 * t + 1;
    const int c0 = (i0 < N_URLS) ? s_cnt[i0] : 0;
    const int c1 = (i1 < N_URLS) ? s_cnt[i1] : 0;

    // scan 1: token offsets
    const int pair = c0 + c1;
    int incl = warp_incl_scan(pair, lane);
    if (lane == 31) s_wsum[wid] = incl;
    __syncthreads();
    if (wid == 0) {
        int v = s_wsum[lane];
        int wi = warp_incl_scan(v, lane);
        s_wsum[lane] = wi - v;
    }
    __syncthreads();
    const int excl = s_wsum[wid] + incl - pair;
    if (i0 < N_URLS) { s_off[i0] = excl;      g_offsets[i0] = excl;      g_counts[i0] = c0; }
    if (i1 < N_URLS) { s_off[i1] = excl + c0; g_offsets[i1] = excl + c0; g_counts[i1] = c1; }
    __syncthreads();

    for (int n = t; n < N_TOKENS; n += 1024) {
        const int u = urls[n];
        const int pos = atomicAdd(&s_cur[u], 1);
        g_token_list[s_off[u] + pos] = n;
    }

    // scan 2: item offsets (ceil(count/8) per url)
    const int nch0 = (c0 + CHUNK - 1) >> 3;
    const int nch1 = (c1 + CHUNK - 1) >> 3;
    const int pair2 = nch0 + nch1;
    int incl2 = warp_incl_scan(pair2, lane);
    if (lane == 31) s_wsum2[wid] = incl2;
    __syncthreads();
    if (wid == 0) {
        int v = s_wsum2[lane];
        int wi = warp_incl_scan(v, lane);
        s_wsum2[lane] = wi - v;
    }
    __syncthreads();
    const int excl2 = s_wsum2[wid] + incl2 - pair2;
    if (i0 < N_URLS)
        for (int j = 0; j < nch0; j++) g_items[excl2 + j] = (i0 << 12) | (j * CHUNK);
    if (i1 < N_URLS)
        for (int j = 0; j < nch1; j++) g_items[excl2 + nch0 + j] = (i1 << 12) | (j * CHUNK);
    if (t == 1023) g_nitems = s_wsum2[31] + incl2;
}

// ---- main: persistent CTAs, continuous 2x16KB bulk-async ring ----
// 128 threads; thread t owns output columns t and t+128.
// k<=4 path: 8 accumulators (proven fast loop); k>=5 path: 16 accumulators.
__global__ __launch_bounds__(128)
void grouped_kernel(const float* __restrict__ inp,
                    const float* __restrict__ trans,
                    const float* __restrict__ bias,
                    float*       __restrict__ out)
{
    __shared__ float  T_s[NBUF][STAGE_FLOATS];  // 2 x 16KB ring
    __shared__ float4 xs[D * 2];                // 8KB
    __shared__ int    tok_s[CHUNK];
    __shared__ __align__(8) unsigned long long mbar[NBUF];

    const int tid = threadIdx.x;
    const uint32_t mb_base = smem_u32(&mbar[0]);
    const uint32_t tb_base = smem_u32(&T_s[0][0]);

    // prep-independent setup runs while prep kernel is still executing
    if (tid == 0) {
        #pragma unroll
        for (int b = 0; b < NBUF; b++) mbar_init(mb_base + b * 8, 1);
    }
    __syncthreads();

    // wait for prep grid to complete (its stores then globally visible)
    asm volatile("griddepcontrol.wait;" ::: "memory");

    const int nitems = g_nitems;
    int n_my = 0;
    int my_items[MAX_MY];
    for (int unit = blockIdx.x; unit < nitems && n_my < MAX_MY; unit += GRID_MAIN)
        my_items[n_my++] = g_items[unit];
    if (n_my == 0) return;

    const int total = n_my * N_STAGES;
    uint32_t phases = 0;

    // prologue: fill ring (producer runs ahead across unit boundaries)
    if (tid == 0) {
        #pragma unroll
        for (int g = 0; g < NBUF; g++) {
            if (g < total) {
                const float* src = trans
                    + (size_t)(my_items[g >> 4] >> 12) * (D * D)
                    + (size_t)(g & (N_STAGES - 1)) * STAGE_FLOATS;
                mbar_expect_tx(mb_base + g * 8, STAGE_BYTES);
                bulk_g2s(tb_base + g * STAGE_BYTES, src, STAGE_BYTES, mb_base + g * 8);
            }
        }
    }

    int g = 0;
    for (int mi = 0; mi < n_my; mi++) {
        const int item  = my_items[mi];
        const int u     = item >> 12;
        const int cbase = item & 0xFFF;
        const int k     = min(CHUNK, g_counts[u] - cbase);
        const int boff  = g_offsets[u];

        __syncthreads();   // prev epilogue done before tok_s/xs rewrite
        if (tid < CHUNK)
            tok_s[tid] = (tid < k) ? g_token_list[boff + cbase + tid] : 0;
        __syncthreads();

        const float b0 = bias[(size_t)u * D + tid];
        const float b1 = bias[(size_t)u * D + tid + 128];

        if (k <= 4) {
            // ---- fast path ----
            for (int d = tid; d < D; d += 128) {
                float4 v;
                v.x =           inp[(size_t)tok_s[0] * D + d];
                v.y = (k > 1) ? inp[(size_t)tok_s[1] * D + d] : 0.f;
                v.z = (k > 2) ? inp[(size_t)tok_s[2] * D + d] : 0.f;
                v.w = (k > 3) ? inp[(size_t)tok_s[3] * D + d] : 0.f;
                xs[d] = v;
            }
            __syncthreads();

            float4 acc0 = make_float4(0.f, 0.f, 0.f, 0.f);
            float4 acc1 = make_float4(0.f, 0.f, 0.f, 0.f);

            for (int ls = 0; ls < N_STAGES; ls++, g++) {
                const int b = g & (NBUF - 1);
                mbar_wait(mb_base + b * 8, (phases >> b) & 1u);
                phases ^= (1u << b);

                const float* buf = T_s[b];
                const int dbase = ls * ROWS_PER_STAGE;
                #pragma unroll 4
                for (int r = 0; r < ROWS_PER_STAGE; r++) {
                    const float4 x = xs[dbase + r];
                    const float t0 = buf[r * D + tid];
                    const float t1 = buf[r * D + tid + 128];
                    acc0.x = fmaf(x.x, t0, acc0.x);
                    acc0.y = fmaf(x.y, t0, acc0.y);
                    acc0.z = fmaf(x.z, t0, acc0.z);
                    acc0.w = fmaf(x.w, t0, acc0.w);
                    acc1.x = fmaf(x.x, t1, acc1.x);
                    acc1.y = fmaf(x.y, t1, acc1.y);
                    acc1.z = fmaf(x.z, t1, acc1.z);
                    acc1.w = fmaf(x.w, t1, acc1.w);
                }
                __syncthreads();
                if (tid == 0 && g + NBUF < total) {
                    const int gn = g + NBUF;
                    const float* src = trans
                        + (size_t)(my_items[gn >> 4] >> 12) * (D * D)
                        + (size_t)(gn & (N_STAGES - 1)) * STAGE_FLOATS;
                    mbar_expect_tx(mb_base + b * 8, STAGE_BYTES);
                    bulk_g2s(tb_base + b * STAGE_BYTES, src, STAGE_BYTES, mb_base + b * 8);
                }
            }

            const float* a0 = (const float*)&acc0;
            const float* a1 = (const float*)&acc1;
            #pragma unroll
            for (int kk = 0; kk < 4; kk++) {
                if (kk < k) {
                    const size_t nb = (size_t)tok_s[kk] * D;
                    out[nb + tid]       = tanhf(a0[kk] + b0);
                    out[nb + tid + 128] = tanhf(a1[kk] + b1);
                }
            }
        } else {
            // ---- heavy path: 5..8 tokens, one matrix stream ----
            for (int d = tid; d < D; d += 128) {
                float4 lo, hi;
                lo.x =           inp[(size_t)tok_s[0] * D + d];
                lo.y =           inp[(size_t)tok_s[1] * D + d];
                lo.z =           inp[(size_t)tok_s[2] * D + d];
                lo.w =           inp[(size_t)tok_s[3] * D + d];
                hi.x =           inp[(size_t)tok_s[4] * D + d];
                hi.y = (k > 5) ? inp[(size_t)tok_s[5] * D + d] : 0.f;
                hi.z = (k > 6) ? inp[(size_t)tok_s[6] * D + d] : 0.f;
                hi.w = (k > 7) ? inp[(size_t)tok_s[7] * D + d] : 0.f;
                xs[d * 2]     = lo;
                xs[d * 2 + 1] = hi;
            }
            __syncthreads();

            float accA[CHUNK], accB[CHUNK];
            #pragma unroll
            for (int q = 0; q < CHUNK; q++) { accA[q] = 0.f; accB[q] = 0.f; }

            for (int ls = 0; ls < N_STAGES; ls++, g++) {
                const int b = g & (NBUF - 1);
                mbar_wait(mb_base + b * 8, (phases >> b) & 1u);
                phases ^= (1u << b);

                const float* buf = T_s[b];
                const int dbase = ls * ROWS_PER_STAGE;
                #pragma unroll 2
                for (int r = 0; r < ROWS_PER_STAGE; r++) {
                    const float4 xlo = xs[(dbase + r) * 2];
                    const float4 xhi = xs[(dbase + r) * 2 + 1];
                    const float t0 = buf[r * D + tid];
                    const float t1 = buf[r * D + tid + 128];
                    accA[0] = fmaf(xlo.x, t0, accA[0]);
                    accA[1] = fmaf(xlo.y, t0, accA[1]);
                    accA[2] = fmaf(xlo.z, t0, accA[2]);
                    accA[3] = fmaf(xlo.w, t0, accA[3]);
                    accA[4] = fmaf(xhi.x, t0, accA[4]);
                    accA[5] = fmaf(xhi.y, t0, accA[5]);
                    accA[6] = fmaf(xhi.z, t0, accA[6]);
                    accA[7] = fmaf(xhi.w, t0, accA[7]);
                    accB[0] = fmaf(xlo.x, t1, accB[0]);
                    accB[1] = fmaf(xlo.y, t1, accB[1]);
                    accB[2] = fmaf(xlo.z, t1, accB[2]);
                    accB[3] = fmaf(xlo.w, t1, accB[3]);
                    accB[4] = fmaf(xhi.x, t1, accB[4]);
                    accB[5] = fmaf(xhi.y, t1, accB[5]);
                    accB[6] = fmaf(xhi.z, t1, accB[6]);
                    accB[7] = fmaf(xhi.w, t1, accB[7]);
                }
                __syncthreads();
                if (tid == 0 && g + NBUF < total) {
                    const int gn = g + NBUF;
                    const float* src = trans
                        + (size_t)(my_items[gn >> 4] >> 12) * (D * D)
                        + (size_t)(gn & (N_STAGES - 1)) * STAGE_FLOATS;
                    mbar_expect_tx(mb_base + b * 8, STAGE_BYTES);
                    bulk_g2s(tb_base + b * STAGE_BYTES, src, STAGE_BYTES, mb_base + b * 8);
                }
            }

            #pragma unroll
            for (int q = 0; q < CHUNK; q++) {
                if (q < k) {
                    const size_t nb = (size_t)tok_s[q] * D;
                    out[nb + tid]       = tanhf(accA[q] + b0);
                    out[nb + tid + 128] = tanhf(accB[q] + b1);
                }
            }
        }
    }
}

extern "C" void kernel_launch(void* const* d_in, const int* in_sizes, int n_in,
                              void* d_out, int out_size)
{
    const float* inp   = (const float*)d_in[0];
    const int*   urls  = (const int*)  d_in[1];
    const float* trans = (const float*)d_in[2];
    const float* bias  = (const float*)d_in[3];
    float*       out   = (float*)      d_out;

    prep_kernel<<<1, 1024>>>(urls);

    // main kernel with PDL: launches (and runs its prep-independent prologue)
    // while prep is still executing; blocks at griddepcontrol.wait.
    cudaLaunchConfig_t cfg = {};
    cfg.gridDim  = dim3(GRID_MAIN, 1, 1);
    cfg.blockDim = dim3(128, 1, 1);
    cfg.dynamicSmemBytes = 0;
    cfg.stream = 0;   // legacy default stream (same as prep)
    cudaLaunchAttribute attrs[1];
    attrs[0].id = cudaLaunchAttributeProgrammaticStreamSerialization;
    attrs[0].val.programmaticStreamSerializationAllowed = 1;
    cfg.attrs = attrs;
    cfg.numAttrs = 1;
    cudaLaunchKernelEx(&cfg, grouped_kernel, inp, trans, bias, out);
}